// round 14
// baseline (speedup 1.0000x reference)
#include <cuda_runtime.h>
#include <cuda_fp16.h>
#include <cstdint>

// ---------------------------------------------------------------------------
// GRUCell: out = gru(LayerNorm(concat(x,h) @ W^T + b))
//   B=8192, IN=2048, H=4096, K=6144, N=3H=12288
//
// compute_103 PTX target: no tcgen05/TMEM. Register-path mma.sync fp16.
// R13: rotated mainloop — post-barrier LDSM(ks=0) first, then cp.async
//      prefetch under it, then MMA(ks)/LDSM(ks+1) rotation (single buffer).
//      Keeps 2-CTA/SM (BM=BN=128, BK=64, 3 stages), fp16 g_parts, fast gates.
// ---------------------------------------------------------------------------

#define B_ROWS   8192
#define IN_DIM   2048
#define H_DIM    4096
#define K_TOT    6144
#define N_TOT    12288

#define BM 128
#define BN 128
#define BK 64
#define STAGES 3
#define NK_TILES (K_TOT / BK)        // 96
#define MT (B_ROWS / BM)             // 64
#define NT (N_TOT / BN)              // 96
#define GROUP_M 16

#define LDA (BK + 8)                 // 72 halves; stride 36 words = 4 mod 32
#define A_STAGE_BYTES (BM * LDA * 2)            // 18432
#define B_STAGE_BYTES (BN * LDA * 2)            // 18432
#define STAGE_BYTES (A_STAGE_BYTES + B_STAGE_BYTES)   // 36864
#define GEMM_SMEM (STAGES * STAGE_BYTES)        // 110592 B -> 2 CTAs/SM

__device__ __half g_a[(size_t)B_ROWS * K_TOT];      // fp16 [x|h]
__device__ __half g_w[(size_t)N_TOT * K_TOT];       // fp16 W
__device__ __half g_parts[(size_t)B_ROWS * N_TOT];  // fp16 GEMM out (pre-LN)

// ------------------------------ helpers ------------------------------------
__device__ __forceinline__ uint32_t smem_u32(const void* p) {
    uint32_t a;
    asm("{ .reg .u64 t; cvta.to.shared.u64 t, %1; cvt.u32.u64 %0, t; }" : "=r"(a) : "l"(p));
    return a;
}
__device__ __forceinline__ void cp16(uint32_t s, const void* g) {
    asm volatile("cp.async.cg.shared.global [%0], [%1], 16;" :: "r"(s), "l"(g));
}
__device__ __forceinline__ void mma_f16(float* d, const uint32_t* a, const uint32_t* b) {
    asm volatile(
        "mma.sync.aligned.m16n8k16.row.col.f32.f16.f16.f32 "
        "{%0,%1,%2,%3}, {%4,%5,%6,%7}, {%8,%9}, {%0,%1,%2,%3};"
        : "+f"(d[0]), "+f"(d[1]), "+f"(d[2]), "+f"(d[3])
        : "r"(a[0]), "r"(a[1]), "r"(a[2]), "r"(a[3]), "r"(b[0]), "r"(b[1]));
}
#define LDSM4(r0, r1, r2, r3, addr) \
    asm volatile("ldmatrix.sync.aligned.m8n8.x4.shared.b16 {%0,%1,%2,%3}, [%4];" \
        : "=r"(r0), "=r"(r1), "=r"(r2), "=r"(r3) : "r"(addr))
__device__ __forceinline__ float fast_tanh(float x) {
    float y;
    asm("tanh.approx.f32 %0, %1;" : "=f"(y) : "f"(x));
    return y;
}
__device__ __forceinline__ float fast_sigmoid(float x) {
    return 1.f / (1.f + __expf(-x));
}

// --------------------------- conversion kernels ----------------------------
__global__ __launch_bounds__(256)
void cvt_a(const float* __restrict__ x, const float* __restrict__ h)
{
    int row = blockIdx.x;
    __half* dst = g_a + (size_t)row * K_TOT;
    const float* xr = x + (size_t)row * IN_DIM;
    const float* hr = h + (size_t)row * H_DIM;
    #pragma unroll
    for (int it = 0; it < 6; it++) {
        int k = threadIdx.x * 4 + it * 1024;
        float4 v = (k < IN_DIM)
            ? *reinterpret_cast<const float4*>(xr + k)
            : *reinterpret_cast<const float4*>(hr + (k - IN_DIM));
        __half2 p0 = __floats2half2_rn(v.x, v.y);
        __half2 p1 = __floats2half2_rn(v.z, v.w);
        *reinterpret_cast<uint2*>(dst + k) =
            make_uint2(*reinterpret_cast<uint32_t*>(&p0), *reinterpret_cast<uint32_t*>(&p1));
    }
}

__global__ __launch_bounds__(256)
void cvt_w(const float* __restrict__ W)
{
    size_t i = ((size_t)blockIdx.x * 256 + threadIdx.x) * 8;
    float4 v0 = *reinterpret_cast<const float4*>(W + i);
    float4 v1 = *reinterpret_cast<const float4*>(W + i + 4);
    __half2 p0 = __floats2half2_rn(v0.x, v0.y);
    __half2 p1 = __floats2half2_rn(v0.z, v0.w);
    __half2 p2 = __floats2half2_rn(v1.x, v1.y);
    __half2 p3 = __floats2half2_rn(v1.z, v1.w);
    *reinterpret_cast<uint4*>(g_w + i) = make_uint4(
        *reinterpret_cast<uint32_t*>(&p0), *reinterpret_cast<uint32_t*>(&p1),
        *reinterpret_cast<uint32_t*>(&p2), *reinterpret_cast<uint32_t*>(&p3));
}

// --------------------------- tile load (cp.async) --------------------------
__device__ __forceinline__ void load_tile(
    int kt, uint32_t a_base, uint32_t b_base, size_t rowA0, size_t rowB0, int tid)
{
    int ko = kt * BK;
    #pragma unroll
    for (int j = 0; j < 4; j++) {
        int idx = tid + j * 256;
        int row = idx >> 3, ck = idx & 7;
        cp16(a_base + (uint32_t)(row * LDA + ck * 8) * 2,
             g_a + (rowA0 + (size_t)row) * K_TOT + ko + ck * 8);
    }
    #pragma unroll
    for (int j = 0; j < 4; j++) {
        int idx = tid + j * 256;
        int row = idx >> 3, ck = idx & 7;
        cp16(b_base + (uint32_t)(row * LDA + ck * 8) * 2,
             g_w + (rowB0 + (size_t)row) * K_TOT + ko + ck * 8);
    }
}

// ------------------------------- GEMM kernel -------------------------------
extern __shared__ __half dynsmem_h[];

__global__ __launch_bounds__(256, 2)
void gemm_f16(void)
{
    uint32_t sb = smem_u32(dynsmem_h);
    int tid = threadIdx.x;
    int wid = tid >> 5, lane = tid & 31;
    int wm = wid >> 2, wn = wid & 3;          // 2 x 4 warp grid, 64x32 warp tiles
    int lr = lane >> 2, lc = lane & 3;
    int r8 = lane & 7, seg = lane >> 3;       // ldmatrix addressing

    int bid = blockIdx.x;
    int g = bid / (GROUP_M * NT);
    int r = bid % (GROUP_M * NT);
    int tm = g * GROUP_M + (r % GROUP_M);
    int tn = r / GROUP_M;
    size_t rowA0 = (size_t)tm * BM;
    size_t rowB0 = (size_t)tn * BN;

    uint32_t a_off0 = (uint32_t)((wm * 64 + r8 + (seg & 1) * 8) * LDA + (seg >> 1) * 8);
    uint32_t b_off0 = (uint32_t)((wn * 32 + r8 + (seg >> 1) * 8) * LDA + (seg & 1) * 8);

    float acc[4][4][4];
    #pragma unroll
    for (int mi = 0; mi < 4; mi++)
        #pragma unroll
        for (int ni = 0; ni < 4; ni++)
            #pragma unroll
            for (int q = 0; q < 4; q++) acc[mi][ni][q] = 0.f;

    #pragma unroll
    for (int t = 0; t < STAGES - 1; t++) {
        uint32_t ab = sb + t * STAGE_BYTES;
        load_tile(t, ab, ab + A_STAGE_BYTES, rowA0, rowB0, tid);
        asm volatile("cp.async.commit_group;" ::: "memory");
    }

    for (int kt = 0; kt < NK_TILES; kt++) {
        int s = kt % STAGES;
        asm volatile("cp.async.wait_group 1;" ::: "memory");
        __syncthreads();

        uint32_t As = sb + s * STAGE_BYTES;
        uint32_t Bs = As + A_STAGE_BYTES;

        // 1) LDSM for ks=0 FIRST (stage s is ready; start the loads now)
        uint32_t af[4][4];
        uint32_t bf[4][2];
        #pragma unroll
        for (int mi = 0; mi < 4; mi++) {
            uint32_t addr = As + (a_off0 + (uint32_t)(mi * 16 * LDA)) * 2;
            LDSM4(af[mi][0], af[mi][1], af[mi][2], af[mi][3], addr);
        }
        #pragma unroll
        for (int np = 0; np < 2; np++) {
            uint32_t addr = Bs + (b_off0 + (uint32_t)(np * 16 * LDA)) * 2;
            LDSM4(bf[2 * np][0], bf[2 * np][1], bf[2 * np + 1][0], bf[2 * np + 1][1], addr);
        }

        // 2) prefetch kt+2 under the LDSM latency
        int tnext = kt + STAGES - 1;
        if (tnext < NK_TILES) {
            int sn = tnext % STAGES;
            uint32_t ab = sb + sn * STAGE_BYTES;
            load_tile(tnext, ab, ab + A_STAGE_BYTES, rowA0, rowB0, tid);
        }
        asm volatile("cp.async.commit_group;" ::: "memory");

        // 3) rotated compute: MMA(ks) then LDSM(ks+1) into the same regs
        #pragma unroll
        for (int ks = 0; ks < 4; ks++) {               // BK=64 -> 4 x k16 steps
            #pragma unroll
            for (int mi = 0; mi < 4; mi++)
                #pragma unroll
                for (int ni = 0; ni < 4; ni++)
                    mma_f16(acc[mi][ni], af[mi], bf[ni]);
            if (ks < 3) {
                #pragma unroll
                for (int mi = 0; mi < 4; mi++) {
                    uint32_t addr = As + (a_off0 + (uint32_t)(mi * 16 * LDA + (ks + 1) * 16)) * 2;
                    LDSM4(af[mi][0], af[mi][1], af[mi][2], af[mi][3], addr);
                }
                #pragma unroll
                for (int np = 0; np < 2; np++) {
                    uint32_t addr = Bs + (b_off0 + (uint32_t)(np * 16 * LDA + (ks + 1) * 16)) * 2;
                    LDSM4(bf[2 * np][0], bf[2 * np][1],
                          bf[2 * np + 1][0], bf[2 * np + 1][1], addr);
                }
            }
        }
    }

    // epilogue: fp16 stores to g_parts
    #pragma unroll
    for (int mi = 0; mi < 4; mi++) {
        size_t row0 = rowA0 + wm * 64 + mi * 16 + lr;
        #pragma unroll
        for (int ni = 0; ni < 4; ni++) {
            size_t col = rowB0 + wn * 32 + ni * 8 + 2 * lc;
            __half2 v0 = __floats2half2_rn(acc[mi][ni][0], acc[mi][ni][1]);
            __half2 v1 = __floats2half2_rn(acc[mi][ni][2], acc[mi][ni][3]);
            *reinterpret_cast<__half2*>(g_parts + row0 * N_TOT + col) = v0;
            *reinterpret_cast<__half2*>(g_parts + (row0 + 8) * N_TOT + col) = v1;
        }
    }
}

// --------------------------- LayerNorm + GRU gates -------------------------
extern __shared__ float lnsmem[];

__global__ __launch_bounds__(512)
void ln_gate(const float* __restrict__ st, const float* __restrict__ bias,
             const float* __restrict__ gam, const float* __restrict__ bet,
             float* __restrict__ out)
{
    float* rowbuf = lnsmem;                     // 12288 fp32
    __shared__ float wsum[16], wsum2[16];
    int tid = threadIdx.x;
    size_t rb = (size_t)blockIdx.x * N_TOT;

    float s = 0.f, s2 = 0.f;
    #pragma unroll 3
    for (int i = tid * 8; i < N_TOT; i += 4096) {
        uint4 raw = *reinterpret_cast<const uint4*>(g_parts + rb + i);
        float4 b0 = *reinterpret_cast<const float4*>(bias + i);
        float4 b1 = *reinterpret_cast<const float4*>(bias + i + 4);
        float2 c0 = __half22float2(*reinterpret_cast<__half2*>(&raw.x));
        float2 c1 = __half22float2(*reinterpret_cast<__half2*>(&raw.y));
        float2 c2 = __half22float2(*reinterpret_cast<__half2*>(&raw.z));
        float2 c3 = __half22float2(*reinterpret_cast<__half2*>(&raw.w));
        float v0 = c0.x + b0.x, v1 = c0.y + b0.y, v2 = c1.x + b0.z, v3 = c1.y + b0.w;
        float v4 = c2.x + b1.x, v5 = c2.y + b1.y, v6 = c3.x + b1.z, v7 = c3.y + b1.w;
        *reinterpret_cast<float4*>(rowbuf + i)     = make_float4(v0, v1, v2, v3);
        *reinterpret_cast<float4*>(rowbuf + i + 4) = make_float4(v4, v5, v6, v7);
        s  += v0 + v1 + v2 + v3 + v4 + v5 + v6 + v7;
        s2 += v0*v0 + v1*v1 + v2*v2 + v3*v3 + v4*v4 + v5*v5 + v6*v6 + v7*v7;
    }
    #pragma unroll
    for (int o = 16; o; o >>= 1) {
        s  += __shfl_xor_sync(0xFFFFFFFFu, s,  o);
        s2 += __shfl_xor_sync(0xFFFFFFFFu, s2, o);
    }
    if ((tid & 31) == 0) { wsum[tid >> 5] = s; wsum2[tid >> 5] = s2; }
    __syncthreads();
    float S = 0.f, S2 = 0.f;
    #pragma unroll
    for (int w2 = 0; w2 < 16; w2++) { S += wsum[w2]; S2 += wsum2[w2]; }
    const float invN = 1.f / (float)N_TOT;
    float mu = S * invN;
    float var = S2 * invN - mu * mu;
    float rs = rsqrtf(var + 1e-5f);

    size_t ob = (size_t)blockIdx.x * H_DIM;
    #pragma unroll 2
    for (int j = tid * 4; j < H_DIM; j += 2048) {
        float4 rv = *reinterpret_cast<const float4*>(rowbuf + j);
        float4 cv = *reinterpret_cast<const float4*>(rowbuf + j + H_DIM);
        float4 uv = *reinterpret_cast<const float4*>(rowbuf + j + 2 * H_DIM);
        float4 g0 = *reinterpret_cast<const float4*>(gam + j);
        float4 g1 = *reinterpret_cast<const float4*>(gam + j + H_DIM);
        float4 g2 = *reinterpret_cast<const float4*>(gam + j + 2 * H_DIM);
        float4 b0 = *reinterpret_cast<const float4*>(bet + j);
        float4 b1 = *reinterpret_cast<const float4*>(bet + j + H_DIM);
        float4 b2 = *reinterpret_cast<const float4*>(bet + j + 2 * H_DIM);
        float4 hv = *reinterpret_cast<const float4*>(st + ob + j);
        float4 ov;
        {
            float rr = (rv.x - mu) * rs * g0.x + b0.x;
            float cc = (cv.x - mu) * rs * g1.x + b1.x;
            float uu = (uv.x - mu) * rs * g2.x + b2.x;
            float rg = fast_sigmoid(rr);
            float cg = fast_tanh(rg * cc);
            float ug = fast_sigmoid(uu - 1.f);            // UPDATE_BIAS = -1
            ov.x = ug * cg + (1.f - ug) * hv.x;
        }
        {
            float rr = (rv.y - mu) * rs * g0.y + b0.y;
            float cc = (cv.y - mu) * rs * g1.y + b1.y;
            float uu = (uv.y - mu) * rs * g2.y + b2.y;
            float rg = fast_sigmoid(rr);
            float cg = fast_tanh(rg * cc);
            float ug = fast_sigmoid(uu - 1.f);
            ov.y = ug * cg + (1.f - ug) * hv.y;
        }
        {
            float rr = (rv.z - mu) * rs * g0.z + b0.z;
            float cc = (cv.z - mu) * rs * g1.z + b1.z;
            float uu = (uv.z - mu) * rs * g2.z + b2.z;
            float rg = fast_sigmoid(rr);
            float cg = fast_tanh(rg * cc);
            float ug = fast_sigmoid(uu - 1.f);
            ov.z = ug * cg + (1.f - ug) * hv.z;
        }
        {
            float rr = (rv.w - mu) * rs * g0.w + b0.w;
            float cc = (cv.w - mu) * rs * g1.w + b1.w;
            float uu = (uv.w - mu) * rs * g2.w + b2.w;
            float rg = fast_sigmoid(rr);
            float cg = fast_tanh(rg * cc);
            float ug = fast_sigmoid(uu - 1.f);
            ov.w = ug * cg + (1.f - ug) * hv.w;
        }
        *reinterpret_cast<float4*>(out + ob + j) = ov;
    }
}

// ------------------------------ entry point --------------------------------
extern "C" void kernel_launch(void* const* d_in, const int* in_sizes, int n_in,
                              void* d_out, int out_size)
{
    const float* inp  = (const float*)d_in[0];   // [8192, 2048]
    const float* st   = (const float*)d_in[1];   // [8192, 4096]
    const float* W    = (const float*)d_in[2];   // [12288, 6144]
    const float* bias = (const float*)d_in[3];   // [12288]
    const float* gam  = (const float*)d_in[4];   // [12288]
    const float* bet  = (const float*)d_in[5];   // [12288]
    float* out = (float*)d_out;                  // [8192, 4096]

    static cudaStream_t s2 = nullptr;
    static cudaEvent_t ev_fork = nullptr, ev_w = nullptr;
    static bool attr_done = false;
    if (!s2) {
        cudaStreamCreateWithFlags(&s2, cudaStreamNonBlocking);
        cudaEventCreateWithFlags(&ev_fork, cudaEventDisableTiming);
        cudaEventCreateWithFlags(&ev_w,    cudaEventDisableTiming);
    }
    if (!attr_done) {
        cudaFuncSetAttribute(gemm_f16, cudaFuncAttributeMaxDynamicSharedMemorySize, GEMM_SMEM);
        cudaFuncSetAttribute(ln_gate,  cudaFuncAttributeMaxDynamicSharedMemorySize, N_TOT * 4);
        attr_done = true;
    }

    // cvt_w on s2 concurrent with cvt_a on main stream
    cudaEventRecord(ev_fork, 0);
    cudaStreamWaitEvent(s2, ev_fork, 0);
    cvt_w<<<(int)(((size_t)N_TOT * K_TOT) / (256 * 8)), 256, 0, s2>>>(W);
    cudaEventRecord(ev_w, s2);
    cvt_a<<<B_ROWS, 256>>>(inp, st);
    cudaStreamWaitEvent(0, ev_w, 0);

    gemm_f16<<<MT * NT, 256, GEMM_SMEM>>>();
    ln_gate<<<B_ROWS, 512, N_TOT * 4>>>(st, bias, gam, bet, out);
}

// round 15
// speedup vs baseline: 1.0277x; 1.0277x over previous
#include <cuda_runtime.h>
#include <cuda_fp16.h>
#include <cstdint>

// ---------------------------------------------------------------------------
// GRUCell: out = gru(LayerNorm(concat(x,h) @ W^T + b))
//   B=8192, IN=2048, H=4096, K=6144, N=3H=12288
//
// compute_103 PTX target: no tcgen05/TMEM. Register-path mma.sync fp16.
// R14: GEMM epilogue fuses bias-add + per-row sum/sumsq (atomicAdd) so
//      ln_gate needs no stats pass / no smem rowbuf (single gating sweep).
//      GEMM mainloop identical to best-known R12 (2 CTAs/SM, BM=BN=128,
//      BK=64, 3 stages, ldmatrix).
// ---------------------------------------------------------------------------

#define B_ROWS   8192
#define IN_DIM   2048
#define H_DIM    4096
#define K_TOT    6144
#define N_TOT    12288

#define BM 128
#define BN 128
#define BK 64
#define STAGES 3
#define NK_TILES (K_TOT / BK)        // 96
#define MT (B_ROWS / BM)             // 64
#define NT (N_TOT / BN)              // 96
#define GROUP_M 16

#define LDA (BK + 8)                 // 72 halves; stride 36 words = 4 mod 32
#define A_STAGE_BYTES (BM * LDA * 2)            // 18432
#define B_STAGE_BYTES (BN * LDA * 2)            // 18432
#define STAGE_BYTES (A_STAGE_BYTES + B_STAGE_BYTES)   // 36864
#define GEMM_SMEM (STAGES * STAGE_BYTES)        // 110592 B -> 2 CTAs/SM

__device__ __half g_a[(size_t)B_ROWS * K_TOT];      // fp16 [x|h]
__device__ __half g_w[(size_t)N_TOT * K_TOT];       // fp16 W
__device__ __half g_parts[(size_t)B_ROWS * N_TOT];  // fp16 GEMM out (+bias)
__device__ float  g_rsum[B_ROWS];                   // per-row sum
__device__ float  g_rsum2[B_ROWS];                  // per-row sum of squares

// ------------------------------ helpers ------------------------------------
__device__ __forceinline__ uint32_t smem_u32(const void* p) {
    uint32_t a;
    asm("{ .reg .u64 t; cvta.to.shared.u64 t, %1; cvt.u32.u64 %0, t; }" : "=r"(a) : "l"(p));
    return a;
}
__device__ __forceinline__ void cp16(uint32_t s, const void* g) {
    asm volatile("cp.async.cg.shared.global [%0], [%1], 16;" :: "r"(s), "l"(g));
}
__device__ __forceinline__ void mma_f16(float* d, const uint32_t* a, const uint32_t* b) {
    asm volatile(
        "mma.sync.aligned.m16n8k16.row.col.f32.f16.f16.f32 "
        "{%0,%1,%2,%3}, {%4,%5,%6,%7}, {%8,%9}, {%0,%1,%2,%3};"
        : "+f"(d[0]), "+f"(d[1]), "+f"(d[2]), "+f"(d[3])
        : "r"(a[0]), "r"(a[1]), "r"(a[2]), "r"(a[3]), "r"(b[0]), "r"(b[1]));
}
#define LDSM4(r0, r1, r2, r3, addr) \
    asm volatile("ldmatrix.sync.aligned.m8n8.x4.shared.b16 {%0,%1,%2,%3}, [%4];" \
        : "=r"(r0), "=r"(r1), "=r"(r2), "=r"(r3) : "r"(addr))
__device__ __forceinline__ float fast_tanh(float x) {
    float y;
    asm("tanh.approx.f32 %0, %1;" : "=f"(y) : "f"(x));
    return y;
}
__device__ __forceinline__ float fast_sigmoid(float x) {
    return 1.f / (1.f + __expf(-x));
}

// --------------------------- init / conversion kernels ---------------------
__global__ __launch_bounds__(256)
void zero_stats(void)
{
    int i = blockIdx.x * 256 + threadIdx.x;
    g_rsum[i] = 0.f;
    g_rsum2[i] = 0.f;
}

__global__ __launch_bounds__(256)
void cvt_a(const float* __restrict__ x, const float* __restrict__ h)
{
    int row = blockIdx.x;
    __half* dst = g_a + (size_t)row * K_TOT;
    const float* xr = x + (size_t)row * IN_DIM;
    const float* hr = h + (size_t)row * H_DIM;
    #pragma unroll
    for (int it = 0; it < 6; it++) {
        int k = threadIdx.x * 4 + it * 1024;
        float4 v = (k < IN_DIM)
            ? *reinterpret_cast<const float4*>(xr + k)
            : *reinterpret_cast<const float4*>(hr + (k - IN_DIM));
        __half2 p0 = __floats2half2_rn(v.x, v.y);
        __half2 p1 = __floats2half2_rn(v.z, v.w);
        *reinterpret_cast<uint2*>(dst + k) =
            make_uint2(*reinterpret_cast<uint32_t*>(&p0), *reinterpret_cast<uint32_t*>(&p1));
    }
}

__global__ __launch_bounds__(256)
void cvt_w(const float* __restrict__ W)
{
    size_t i = ((size_t)blockIdx.x * 256 + threadIdx.x) * 8;
    float4 v0 = *reinterpret_cast<const float4*>(W + i);
    float4 v1 = *reinterpret_cast<const float4*>(W + i + 4);
    __half2 p0 = __floats2half2_rn(v0.x, v0.y);
    __half2 p1 = __floats2half2_rn(v0.z, v0.w);
    __half2 p2 = __floats2half2_rn(v1.x, v1.y);
    __half2 p3 = __floats2half2_rn(v1.z, v1.w);
    *reinterpret_cast<uint4*>(g_w + i) = make_uint4(
        *reinterpret_cast<uint32_t*>(&p0), *reinterpret_cast<uint32_t*>(&p1),
        *reinterpret_cast<uint32_t*>(&p2), *reinterpret_cast<uint32_t*>(&p3));
}

// --------------------------- tile load (cp.async) --------------------------
__device__ __forceinline__ void load_tile(
    int kt, uint32_t a_base, uint32_t b_base, size_t rowA0, size_t rowB0, int tid)
{
    int ko = kt * BK;
    #pragma unroll
    for (int j = 0; j < 4; j++) {
        int idx = tid + j * 256;
        int row = idx >> 3, ck = idx & 7;
        cp16(a_base + (uint32_t)(row * LDA + ck * 8) * 2,
             g_a + (rowA0 + (size_t)row) * K_TOT + ko + ck * 8);
    }
    #pragma unroll
    for (int j = 0; j < 4; j++) {
        int idx = tid + j * 256;
        int row = idx >> 3, ck = idx & 7;
        cp16(b_base + (uint32_t)(row * LDA + ck * 8) * 2,
             g_w + (rowB0 + (size_t)row) * K_TOT + ko + ck * 8);
    }
}

// ------------------------------- GEMM kernel -------------------------------
extern __shared__ __half dynsmem_h[];

__global__ __launch_bounds__(256, 2)
void gemm_f16(const float* __restrict__ bias)
{
    uint32_t sb = smem_u32(dynsmem_h);
    int tid = threadIdx.x;
    int wid = tid >> 5, lane = tid & 31;
    int wm = wid >> 2, wn = wid & 3;          // 2 x 4 warp grid, 64x32 warp tiles
    int lr = lane >> 2, lc = lane & 3;
    int r8 = lane & 7, seg = lane >> 3;       // ldmatrix addressing

    int bid = blockIdx.x;
    int g = bid / (GROUP_M * NT);
    int r = bid % (GROUP_M * NT);
    int tm = g * GROUP_M + (r % GROUP_M);
    int tn = r / GROUP_M;
    size_t rowA0 = (size_t)tm * BM;
    size_t rowB0 = (size_t)tn * BN;

    uint32_t a_off0 = (uint32_t)((wm * 64 + r8 + (seg & 1) * 8) * LDA + (seg >> 1) * 8);
    uint32_t b_off0 = (uint32_t)((wn * 32 + r8 + (seg >> 1) * 8) * LDA + (seg & 1) * 8);

    float acc[4][4][4];
    #pragma unroll
    for (int mi = 0; mi < 4; mi++)
        #pragma unroll
        for (int ni = 0; ni < 4; ni++)
            #pragma unroll
            for (int q = 0; q < 4; q++) acc[mi][ni][q] = 0.f;

    #pragma unroll
    for (int t = 0; t < STAGES - 1; t++) {
        uint32_t ab = sb + t * STAGE_BYTES;
        load_tile(t, ab, ab + A_STAGE_BYTES, rowA0, rowB0, tid);
        asm volatile("cp.async.commit_group;" ::: "memory");
    }

    for (int kt = 0; kt < NK_TILES; kt++) {
        int s = kt % STAGES;
        asm volatile("cp.async.wait_group 1;" ::: "memory");
        __syncthreads();

        int tnext = kt + STAGES - 1;
        if (tnext < NK_TILES) {
            int sn = tnext % STAGES;
            uint32_t ab = sb + sn * STAGE_BYTES;
            load_tile(tnext, ab, ab + A_STAGE_BYTES, rowA0, rowB0, tid);
        }
        asm volatile("cp.async.commit_group;" ::: "memory");

        uint32_t As = sb + s * STAGE_BYTES;
        uint32_t Bs = As + A_STAGE_BYTES;

        #pragma unroll
        for (int ks = 0; ks < 4; ks++) {               // BK=64 -> 4 x k16 steps
            uint32_t af[4][4];
            #pragma unroll
            for (int mi = 0; mi < 4; mi++) {
                uint32_t addr = As + (a_off0 + (uint32_t)(mi * 16 * LDA + ks * 16)) * 2;
                LDSM4(af[mi][0], af[mi][1], af[mi][2], af[mi][3], addr);
            }
            uint32_t bf[4][2];
            #pragma unroll
            for (int np = 0; np < 2; np++) {
                uint32_t addr = Bs + (b_off0 + (uint32_t)(np * 16 * LDA + ks * 16)) * 2;
                LDSM4(bf[2 * np][0], bf[2 * np][1], bf[2 * np + 1][0], bf[2 * np + 1][1], addr);
            }
            #pragma unroll
            for (int mi = 0; mi < 4; mi++)
                #pragma unroll
                for (int ni = 0; ni < 4; ni++)
                    mma_f16(acc[mi][ni], af[mi], bf[ni]);
        }
    }

    // epilogue: bias add, fp16 store, fused per-row sum/sumsq atomics
    #pragma unroll
    for (int mi = 0; mi < 4; mi++) {
        size_t row0 = rowA0 + wm * 64 + mi * 16 + lr;
        float s0 = 0.f, q0 = 0.f, s1 = 0.f, q1 = 0.f;
        #pragma unroll
        for (int ni = 0; ni < 4; ni++) {
            size_t col = rowB0 + wn * 32 + ni * 8 + 2 * lc;
            float2 bv = *reinterpret_cast<const float2*>(bias + col);
            float a0 = acc[mi][ni][0] + bv.x;
            float a1 = acc[mi][ni][1] + bv.y;
            float a2 = acc[mi][ni][2] + bv.x;
            float a3 = acc[mi][ni][3] + bv.y;
            s0 += a0 + a1;  q0 += a0 * a0 + a1 * a1;
            s1 += a2 + a3;  q1 += a2 * a2 + a3 * a3;
            *reinterpret_cast<__half2*>(g_parts + row0 * N_TOT + col) =
                __floats2half2_rn(a0, a1);
            *reinterpret_cast<__half2*>(g_parts + (row0 + 8) * N_TOT + col) =
                __floats2half2_rn(a2, a3);
        }
        // reduce across the 4 lanes of the quad (lane bits 0-1 = lc)
        #pragma unroll
        for (int off = 1; off <= 2; off <<= 1) {
            s0 += __shfl_xor_sync(0xFFFFFFFFu, s0, off);
            q0 += __shfl_xor_sync(0xFFFFFFFFu, q0, off);
            s1 += __shfl_xor_sync(0xFFFFFFFFu, s1, off);
            q1 += __shfl_xor_sync(0xFFFFFFFFu, q1, off);
        }
        if (lc == 0) {
            atomicAdd(&g_rsum[row0], s0);
            atomicAdd(&g_rsum2[row0], q0);
            atomicAdd(&g_rsum[row0 + 8], s1);
            atomicAdd(&g_rsum2[row0 + 8], q1);
        }
    }
}

// --------------------------- GRU gates (stats precomputed) -----------------
__global__ __launch_bounds__(512)
void ln_gate(const float* __restrict__ st, const float* __restrict__ gam,
             const float* __restrict__ bet, float* __restrict__ out)
{
    int row = blockIdx.x;
    int tid = threadIdx.x;
    size_t rb = (size_t)row * N_TOT;
    size_t ob = (size_t)row * H_DIM;

    const float invN = 1.f / (float)N_TOT;
    float mu = g_rsum[row] * invN;
    float var = g_rsum2[row] * invN - mu * mu;
    float rs = rsqrtf(var + 1e-5f);

    #pragma unroll 2
    for (int j = tid * 4; j < H_DIM; j += 2048) {
        uint2 pr = *reinterpret_cast<const uint2*>(g_parts + rb + j);
        uint2 pc = *reinterpret_cast<const uint2*>(g_parts + rb + H_DIM + j);
        uint2 pu = *reinterpret_cast<const uint2*>(g_parts + rb + 2 * H_DIM + j);
        float2 r01 = __half22float2(*reinterpret_cast<__half2*>(&pr.x));
        float2 r23 = __half22float2(*reinterpret_cast<__half2*>(&pr.y));
        float2 c01 = __half22float2(*reinterpret_cast<__half2*>(&pc.x));
        float2 c23 = __half22float2(*reinterpret_cast<__half2*>(&pc.y));
        float2 u01 = __half22float2(*reinterpret_cast<__half2*>(&pu.x));
        float2 u23 = __half22float2(*reinterpret_cast<__half2*>(&pu.y));
        float4 rv = make_float4(r01.x, r01.y, r23.x, r23.y);
        float4 cv = make_float4(c01.x, c01.y, c23.x, c23.y);
        float4 uv = make_float4(u01.x, u01.y, u23.x, u23.y);
        float4 g0 = *reinterpret_cast<const float4*>(gam + j);
        float4 g1 = *reinterpret_cast<const float4*>(gam + j + H_DIM);
        float4 g2 = *reinterpret_cast<const float4*>(gam + j + 2 * H_DIM);
        float4 b0 = *reinterpret_cast<const float4*>(bet + j);
        float4 b1 = *reinterpret_cast<const float4*>(bet + j + H_DIM);
        float4 b2 = *reinterpret_cast<const float4*>(bet + j + 2 * H_DIM);
        float4 hv = *reinterpret_cast<const float4*>(st + ob + j);
        float4 ov;
        {
            float rr = (rv.x - mu) * rs * g0.x + b0.x;
            float cc = (cv.x - mu) * rs * g1.x + b1.x;
            float uu = (uv.x - mu) * rs * g2.x + b2.x;
            float rg = fast_sigmoid(rr);
            float cg = fast_tanh(rg * cc);
            float ug = fast_sigmoid(uu - 1.f);            // UPDATE_BIAS = -1
            ov.x = ug * cg + (1.f - ug) * hv.x;
        }
        {
            float rr = (rv.y - mu) * rs * g0.y + b0.y;
            float cc = (cv.y - mu) * rs * g1.y + b1.y;
            float uu = (uv.y - mu) * rs * g2.y + b2.y;
            float rg = fast_sigmoid(rr);
            float cg = fast_tanh(rg * cc);
            float ug = fast_sigmoid(uu - 1.f);
            ov.y = ug * cg + (1.f - ug) * hv.y;
        }
        {
            float rr = (rv.z - mu) * rs * g0.z + b0.z;
            float cc = (cv.z - mu) * rs * g1.z + b1.z;
            float uu = (uv.z - mu) * rs * g2.z + b2.z;
            float rg = fast_sigmoid(rr);
            float cg = fast_tanh(rg * cc);
            float ug = fast_sigmoid(uu - 1.f);
            ov.z = ug * cg + (1.f - ug) * hv.z;
        }
        {
            float rr = (rv.w - mu) * rs * g0.w + b0.w;
            float cc = (cv.w - mu) * rs * g1.w + b1.w;
            float uu = (uv.w - mu) * rs * g2.w + b2.w;
            float rg = fast_sigmoid(rr);
            float cg = fast_tanh(rg * cc);
            float ug = fast_sigmoid(uu - 1.f);
            ov.w = ug * cg + (1.f - ug) * hv.w;
        }
        *reinterpret_cast<float4*>(out + ob + j) = ov;
    }
}

// ------------------------------ entry point --------------------------------
extern "C" void kernel_launch(void* const* d_in, const int* in_sizes, int n_in,
                              void* d_out, int out_size)
{
    const float* inp  = (const float*)d_in[0];   // [8192, 2048]
    const float* st   = (const float*)d_in[1];   // [8192, 4096]
    const float* W    = (const float*)d_in[2];   // [12288, 6144]
    const float* bias = (const float*)d_in[3];   // [12288]
    const float* gam  = (const float*)d_in[4];   // [12288]
    const float* bet  = (const float*)d_in[5];   // [12288]
    float* out = (float*)d_out;                  // [8192, 4096]

    static cudaStream_t s2 = nullptr;
    static cudaEvent_t ev_fork = nullptr, ev_w = nullptr;
    static bool attr_done = false;
    if (!s2) {
        cudaStreamCreateWithFlags(&s2, cudaStreamNonBlocking);
        cudaEventCreateWithFlags(&ev_fork, cudaEventDisableTiming);
        cudaEventCreateWithFlags(&ev_w,    cudaEventDisableTiming);
    }
    if (!attr_done) {
        cudaFuncSetAttribute(gemm_f16, cudaFuncAttributeMaxDynamicSharedMemorySize, GEMM_SMEM);
        attr_done = true;
    }

    // cvt_w on s2 concurrent with {zero_stats, cvt_a} on main stream
    cudaEventRecord(ev_fork, 0);
    cudaStreamWaitEvent(s2, ev_fork, 0);
    cvt_w<<<(int)(((size_t)N_TOT * K_TOT) / (256 * 8)), 256, 0, s2>>>(W);
    cudaEventRecord(ev_w, s2);
    zero_stats<<<B_ROWS / 256, 256>>>();
    cvt_a<<<B_ROWS, 256>>>(inp, st);
    cudaStreamWaitEvent(0, ev_w, 0);

    gemm_f16<<<MT * NT, 256, GEMM_SMEM>>>(bias);
    ln_gate<<<B_ROWS, 512>>>(st, gam, bet, out);
}